// round 3
// baseline (speedup 1.0000x reference)
#include <cuda_runtime.h>
#include <math.h>

#define B 4
#define L 1024
#define D 512
#define H 8
#define DK 64
#define DF 2048
#define NL 2
#define HWIN 6
#define SCALE 0.125f
#define NEG -1e9f
#define EPS 1e-5f
#define ROWS (B*L)
#define BH (B*H)

// ---- scratch (device globals; no allocations allowed) ----
__device__ float g_q[B*L*D];
__device__ float g_k[B*L*D];
__device__ float g_v[B*L*D];
__device__ float g_x[B*L*D];
__device__ float g_tmp[B*L*D];
__device__ float g_ao[B*L*D];
__device__ float g_ff[B*L*DF];
__device__ float g_scores[(size_t)BH*L*L];   // masked pre-softmax scores (carried across layers)
__device__ float g_probs[(size_t)BH*L*L];    // post-softmax probs

// ============================================================
// Generic SGEMM: C[M,N] = A[M,K] @ W[K,N] + bias[N], optional exact GELU.
// 128x128 tile, BK=8, 256 threads, 8x8 microtile. M%128==0, N%128==0, K%8==0.
// ============================================================
template<int GELU>
__global__ void gemm_kernel(const float* __restrict__ A, const float* __restrict__ W,
                            const float* __restrict__ bias, float* __restrict__ C,
                            int M, int N, int K) {
    __shared__ float As[8][128];
    __shared__ float Ws[8][128];
    int tid = threadIdx.x;
    int tr = tid >> 4, tc = tid & 15;
    int bm = blockIdx.y * 128, bn = blockIdx.x * 128;
    float acc[8][8] = {};

    int arow = tid >> 1;            // 0..127
    int acol = (tid & 1) * 4;       // 0 or 4
    int wrow = tid >> 5;            // 0..7
    int wcol = (tid & 31) * 4;      // 0..124

    const float* Ap = A + (size_t)(bm + arow) * K + acol;
    const float* Wp = W + (size_t)wrow * N + bn + wcol;

    for (int k0 = 0; k0 < K; k0 += 8) {
        float4 av = *(const float4*)(Ap + k0);
        As[acol+0][arow] = av.x; As[acol+1][arow] = av.y;
        As[acol+2][arow] = av.z; As[acol+3][arow] = av.w;
        float4 wv = *(const float4*)(Wp + (size_t)k0 * N);
        *(float4*)&Ws[wrow][wcol] = wv;
        __syncthreads();
        #pragma unroll
        for (int kk = 0; kk < 8; kk++) {
            float ra[8], rw[8];
            #pragma unroll
            for (int i = 0; i < 8; i++) ra[i] = As[kk][tr*8 + i];
            #pragma unroll
            for (int j = 0; j < 8; j++) rw[j] = Ws[kk][tc*8 + j];
            #pragma unroll
            for (int i = 0; i < 8; i++)
                #pragma unroll
                for (int j = 0; j < 8; j++)
                    acc[i][j] += ra[i] * rw[j];
        }
        __syncthreads();
    }

    #pragma unroll
    for (int i = 0; i < 8; i++) {
        int row = bm + tr*8 + i;
        float* Crow = C + (size_t)row * N + bn + tc*8;
        #pragma unroll
        for (int j = 0; j < 8; j++) {
            float vv = acc[i][j] + bias[bn + tc*8 + j];
            if (GELU) vv = 0.5f * vv * (1.0f + erff(vv * 0.70710678118654752f));
            Crow[j] = vv;
        }
    }
}

// ============================================================
// Scores: S[b,h,i,j] = (Q_h[i]·K_h[j])*SCALE (+ prev) with anti-local mask.
// 64x64 output tile per block, 256 threads, 4x4 microtile, K=DK=64.
// ============================================================
__global__ void scores_kernel(const float* __restrict__ q, const float* __restrict__ k,
                              float* __restrict__ scores, int add_prev) {
    int bh = blockIdx.z;
    int b = bh / H, h = bh % H;
    int i0 = blockIdx.y * 64, j0 = blockIdx.x * 64;
    __shared__ float Qs[16][64];
    __shared__ float Ks[16][64];
    int tid = threadIdx.x;
    int tr = tid >> 4, tc = tid & 15;
    float acc[4][4] = {};
    const float* qb = q + (size_t)b*L*D + (size_t)h*DK;
    const float* kb = k + (size_t)b*L*D + (size_t)h*DK;
    int lr = tid >> 2;           // 0..63
    int lc = (tid & 3) * 4;      // 0,4,8,12
    for (int kk0 = 0; kk0 < DK; kk0 += 16) {
        float4 qv = *(const float4*)(qb + (size_t)(i0+lr)*D + kk0 + lc);
        Qs[lc+0][lr]=qv.x; Qs[lc+1][lr]=qv.y; Qs[lc+2][lr]=qv.z; Qs[lc+3][lr]=qv.w;
        float4 kv = *(const float4*)(kb + (size_t)(j0+lr)*D + kk0 + lc);
        Ks[lc+0][lr]=kv.x; Ks[lc+1][lr]=kv.y; Ks[lc+2][lr]=kv.z; Ks[lc+3][lr]=kv.w;
        __syncthreads();
        #pragma unroll
        for (int kk = 0; kk < 16; kk++) {
            float ra[4], rb[4];
            #pragma unroll
            for (int i = 0; i < 4; i++) ra[i] = Qs[kk][tr*4+i];
            #pragma unroll
            for (int j = 0; j < 4; j++) rb[j] = Ks[kk][tc*4+j];
            #pragma unroll
            for (int i = 0; i < 4; i++)
                #pragma unroll
                for (int j = 0; j < 4; j++)
                    acc[i][j] += ra[i] * rb[j];
        }
        __syncthreads();
    }
    float* sb = scores + ((size_t)bh*L + i0)*L + j0;
    #pragma unroll
    for (int i = 0; i < 4; i++) {
        int gi = i0 + tr*4 + i;
        #pragma unroll
        for (int j = 0; j < 4; j++) {
            int gj = j0 + tc*4 + j;
            float s = acc[i][j] * SCALE;
            size_t idx = (size_t)(tr*4+i)*L + tc*4 + j;
            if (add_prev) s += sb[idx];
            int d = gi - gj; d = d < 0 ? -d : d;
            if (d < HWIN) s = NEG;
            sb[idx] = s;
        }
    }
}

// ============================================================
// Softmax over rows of length L=1024. One block (256 thr) per row.
// ============================================================
__global__ void softmax_kernel(const float* __restrict__ in, float* __restrict__ out) {
    int row = blockIdx.x;
    const float4* p = (const float4*)(in + (size_t)row * L);
    float4* o = (float4*)(out + (size_t)row * L);
    int tid = threadIdx.x;
    float4 v = p[tid];
    float m = fmaxf(fmaxf(v.x, v.y), fmaxf(v.z, v.w));
    __shared__ float red[8];
    #pragma unroll
    for (int off = 16; off; off >>= 1) m = fmaxf(m, __shfl_xor_sync(0xffffffffu, m, off));
    if ((tid & 31) == 0) red[tid >> 5] = m;
    __syncthreads();
    m = red[0];
    #pragma unroll
    for (int i = 1; i < 8; i++) m = fmaxf(m, red[i]);
    v.x = __expf(v.x - m); v.y = __expf(v.y - m);
    v.z = __expf(v.z - m); v.w = __expf(v.w - m);
    float s = v.x + v.y + v.z + v.w;
    #pragma unroll
    for (int off = 16; off; off >>= 1) s += __shfl_xor_sync(0xffffffffu, s, off);
    __syncthreads();
    if ((tid & 31) == 0) red[tid >> 5] = s;
    __syncthreads();
    s = red[0];
    #pragma unroll
    for (int i = 1; i < 8; i++) s += red[i];
    float inv = 1.0f / s;
    v.x *= inv; v.y *= inv; v.z *= inv; v.w *= inv;
    o[tid] = v;
}

// ============================================================
// AV: O[b,i,h,:] = sum_m P[b,h,i,m] * V[b,m,h,:]. 64-row tile, full DK=64 cols.
// ============================================================
__global__ void av_kernel(const float* __restrict__ attn, const float* __restrict__ v,
                          float* __restrict__ out) {
    int bh = blockIdx.z;
    int b = bh / H, h = bh % H;
    int i0 = blockIdx.x * 64;
    __shared__ float Pm[16][64];
    __shared__ float Vs[16][64];
    int tid = threadIdx.x;
    int tr = tid >> 4, tc = tid & 15;
    float acc[4][4] = {};
    const float* pb = attn + ((size_t)bh*L + i0)*L;
    const float* vb = v + (size_t)b*L*D + (size_t)h*DK;
    int lr = tid >> 2, lc = (tid & 3)*4;
    int vr = tid >> 4, vc = (tid & 15)*4;
    for (int m0 = 0; m0 < L; m0 += 16) {
        float4 pv = *(const float4*)(pb + (size_t)lr*L + m0 + lc);
        Pm[lc+0][lr]=pv.x; Pm[lc+1][lr]=pv.y; Pm[lc+2][lr]=pv.z; Pm[lc+3][lr]=pv.w;
        float4 vv = *(const float4*)(vb + (size_t)(m0+vr)*D + vc);
        *(float4*)&Vs[vr][vc] = vv;
        __syncthreads();
        #pragma unroll
        for (int kk = 0; kk < 16; kk++) {
            float ra[4], rb[4];
            #pragma unroll
            for (int i = 0; i < 4; i++) ra[i] = Pm[kk][tr*4+i];
            #pragma unroll
            for (int j = 0; j < 4; j++) rb[j] = Vs[kk][tc*4+j];
            #pragma unroll
            for (int i = 0; i < 4; i++)
                #pragma unroll
                for (int j = 0; j < 4; j++)
                    acc[i][j] += ra[i] * rb[j];
        }
        __syncthreads();
    }
    float* ob = out + (size_t)b*L*D + (size_t)i0*D + h*DK;
    #pragma unroll
    for (int i = 0; i < 4; i++)
        #pragma unroll
        for (int j = 0; j < 4; j++)
            ob[(size_t)(tr*4+i)*D + tc*4 + j] = acc[i][j];
}

// ============================================================
// out = LayerNorm(x + r) * gamma + beta. One block (128 thr) per row of 512.
// ============================================================
__global__ void addln_kernel(const float* __restrict__ x, const float* __restrict__ r,
                             const float* __restrict__ gam, const float* __restrict__ bet,
                             float* __restrict__ out) {
    int row = blockIdx.x;
    int tid = threadIdx.x;  // 128
    const float4* xp = (const float4*)(x + (size_t)row * D);
    const float4* rp = (const float4*)(r + (size_t)row * D);
    float4 a = xp[tid], b4 = rp[tid];
    float e0 = a.x + b4.x, e1 = a.y + b4.y, e2 = a.z + b4.z, e3 = a.w + b4.w;
    float s = e0 + e1 + e2 + e3;
    float qq = e0*e0 + e1*e1 + e2*e2 + e3*e3;
    __shared__ float rs[4], rq[4];
    #pragma unroll
    for (int off = 16; off; off >>= 1) {
        s  += __shfl_xor_sync(0xffffffffu, s, off);
        qq += __shfl_xor_sync(0xffffffffu, qq, off);
    }
    if ((tid & 31) == 0) { rs[tid >> 5] = s; rq[tid >> 5] = qq; }
    __syncthreads();
    s  = rs[0] + rs[1] + rs[2] + rs[3];
    qq = rq[0] + rq[1] + rq[2] + rq[3];
    float mean = s * (1.0f / D);
    float var  = qq * (1.0f / D) - mean * mean;
    float inv  = rsqrtf(var + EPS);
    float4 g4 = ((const float4*)gam)[tid];
    float4 bb = ((const float4*)bet)[tid];
    float4 ov;
    ov.x = (e0 - mean) * inv * g4.x + bb.x;
    ov.y = (e1 - mean) * inv * g4.y + bb.y;
    ov.z = (e2 - mean) * inv * g4.z + bb.z;
    ov.w = (e3 - mean) * inv * g4.w + bb.w;
    ((float4*)(out + (size_t)row * D))[tid] = ov;
}

// ============================================================
extern "C" void kernel_launch(void* const* d_in, const int* in_sizes, int n_in,
                              void* d_out, int out_size) {
    const float* src = (const float*)d_in[0];
    const float* Wq = (const float*)d_in[1];  const float* bq = (const float*)d_in[2];
    const float* Wk = (const float*)d_in[3];  const float* bk = (const float*)d_in[4];
    const float* Wv = (const float*)d_in[5];  const float* bv = (const float*)d_in[6];
    const float* Wo = (const float*)d_in[7];  const float* bo = (const float*)d_in[8];
    const float* W1 = (const float*)d_in[9];  const float* b1 = (const float*)d_in[10];
    const float* W2 = (const float*)d_in[11]; const float* b2 = (const float*)d_in[12];
    const float* ln1g = (const float*)d_in[13]; const float* ln1b = (const float*)d_in[14];
    const float* ln2g = (const float*)d_in[15]; const float* ln2b = (const float*)d_in[16];

    float *q, *k, *v, *x, *tmp, *ao, *ff, *sc, *pr;
    cudaGetSymbolAddress((void**)&q,  g_q);
    cudaGetSymbolAddress((void**)&k,  g_k);
    cudaGetSymbolAddress((void**)&v,  g_v);
    cudaGetSymbolAddress((void**)&x,  g_x);
    cudaGetSymbolAddress((void**)&tmp, g_tmp);
    cudaGetSymbolAddress((void**)&ao, g_ao);
    cudaGetSymbolAddress((void**)&ff, g_ff);
    cudaGetSymbolAddress((void**)&sc, g_scores);
    cudaGetSymbolAddress((void**)&pr, g_probs);

    dim3 gD(D/128, ROWS/128);    // 4 x 32
    dim3 gDF(DF/128, ROWS/128);  // 16 x 32
    dim3 gS(L/64, L/64, BH);     // 16 x 16 x 32
    dim3 gAV(L/64, 1, BH);       // 16 x 1 x 32

    const float* xin = src;
    for (int l = 0; l < NL; l++) {
        gemm_kernel<0><<<gD, 256>>>(xin, Wq + (size_t)l*D*D, bq + (size_t)l*D, q, ROWS, D, D);
        gemm_kernel<0><<<gD, 256>>>(xin, Wk + (size_t)l*D*D, bk + (size_t)l*D, k, ROWS, D, D);
        gemm_kernel<0><<<gD, 256>>>(xin, Wv + (size_t)l*D*D, bv + (size_t)l*D, v, ROWS, D, D);
        scores_kernel<<<gS, 256>>>(q, k, sc, l > 0 ? 1 : 0);
        softmax_kernel<<<BH*L, 256>>>(sc, pr);
        av_kernel<<<gAV, 256>>>(pr, v, ao);
        gemm_kernel<0><<<gD, 256>>>(ao, Wo + (size_t)l*D*D, bo + (size_t)l*D, tmp, ROWS, D, D);
        addln_kernel<<<ROWS, 128>>>(xin, tmp, ln1g + (size_t)l*D, ln1b + (size_t)l*D, x);
        gemm_kernel<1><<<gDF, 256>>>(x, W1 + (size_t)l*D*DF, b1 + (size_t)l*DF, ff, ROWS, DF, D);
        gemm_kernel<0><<<gD, 256>>>(ff, W2 + (size_t)l*DF*D, b2 + (size_t)l*D, tmp, ROWS, D, DF);
        float* lnout = (l == NL-1) ? (float*)d_out : x;
        addln_kernel<<<ROWS, 128>>>(x, tmp, ln2g + (size_t)l*D, ln2b + (size_t)l*D, lnout);
        xin = x;
    }
}

// round 4
// speedup vs baseline: 2.4157x; 2.4157x over previous
#include <cuda_runtime.h>
#include <math.h>

#define B 4
#define L 1024
#define D 512
#define H 8
#define DK 64
#define DF 2048
#define NL 2
#define HWIN 6
#define SCALE 0.125f
#define NEG -1e9f
#define EPS 1e-5f
#define ROWS (B*L)
#define BH (B*H)

// ---- scratch (device globals; no allocations allowed) ----
__device__ float g_q[B*L*D];
__device__ float g_k[B*L*D];
__device__ float g_v[B*L*D];
__device__ float g_x[B*L*D];
__device__ float g_tmp[B*L*D];
__device__ float g_ao[B*L*D];
__device__ float g_ff[B*L*DF];
__device__ float g_scores[(size_t)BH*L*L];   // masked pre-softmax scores (carried across layers)
__device__ float g_probs[(size_t)BH*L*L];    // post-softmax probs

// ============================================================
// tf32 helpers
// ============================================================
__device__ __forceinline__ float f2tf(float x) {
    unsigned u; asm("cvt.rna.tf32.f32 %0, %1;" : "=r"(u) : "f"(x));
    return __uint_as_float(u);
}
__device__ __forceinline__ void mma8(float* d, const unsigned* a, const unsigned* b) {
    asm volatile("mma.sync.aligned.m16n8k8.row.col.f32.tf32.tf32.f32 "
                 "{%0,%1,%2,%3}, {%4,%5,%6,%7}, {%8,%9}, {%0,%1,%2,%3};\n"
                 : "+f"(d[0]), "+f"(d[1]), "+f"(d[2]), "+f"(d[3])
                 : "r"(a[0]), "r"(a[1]), "r"(a[2]), "r"(a[3]),
                   "r"(b[0]), "r"(b[1]));
}

// ============================================================
// Generic tf32 GEMM: C[M,N] = A[M,K] @ W[K,N] + bias, optional exact GELU.
// 128x128 tile, BK=16, 256 thr (8 warps as 4x2, warptile 32x64),
// register-prefetch double buffering. M%128==0, N%128==0, K%16==0.
// ============================================================
template<int GELU>
__global__ __launch_bounds__(256) void gemm_tf32(const float* __restrict__ A,
                                                 const float* __restrict__ W,
                                                 const float* __restrict__ bias,
                                                 float* __restrict__ C,
                                                 int M, int N, int K) {
    __shared__ float As[2][128][20];
    __shared__ float Bs[2][16][136];
    int tid = threadIdx.x;
    int lane = tid & 31, w = tid >> 5;
    int grp = lane >> 2, tg = lane & 3;
    int wm = (w >> 1) * 32, wn = (w & 1) * 64;
    int bm = blockIdx.y * 128, bn = blockIdx.x * 128;
    int ar = tid >> 1, ac = (tid & 1) * 8;
    int br = tid >> 4, bc = (tid & 15) * 4;

    float acc[2][8][4];
    #pragma unroll
    for (int i = 0; i < 2; i++)
        #pragma unroll
        for (int j = 0; j < 8; j++)
            #pragma unroll
            for (int c = 0; c < 4; c++) acc[i][j][c] = 0.f;

    const float* Ap = A + (size_t)(bm + ar) * K + ac;
    const float* Wp = W + (size_t)br * N + bn + bc;
    int T = K >> 4;

    {   // stage tile 0
        float4 a0 = *(const float4*)(Ap);
        float4 a1 = *(const float4*)(Ap + 4);
        As[0][ar][ac+0]=f2tf(a0.x); As[0][ar][ac+1]=f2tf(a0.y);
        As[0][ar][ac+2]=f2tf(a0.z); As[0][ar][ac+3]=f2tf(a0.w);
        As[0][ar][ac+4]=f2tf(a1.x); As[0][ar][ac+5]=f2tf(a1.y);
        As[0][ar][ac+6]=f2tf(a1.z); As[0][ar][ac+7]=f2tf(a1.w);
        float4 b0 = *(const float4*)(Wp);
        float4 b1 = *(const float4*)(Wp + 64);
        Bs[0][br][bc+0]=f2tf(b0.x); Bs[0][br][bc+1]=f2tf(b0.y);
        Bs[0][br][bc+2]=f2tf(b0.z); Bs[0][br][bc+3]=f2tf(b0.w);
        Bs[0][br][bc+64]=f2tf(b1.x); Bs[0][br][bc+65]=f2tf(b1.y);
        Bs[0][br][bc+66]=f2tf(b1.z); Bs[0][br][bc+67]=f2tf(b1.w);
    }
    __syncthreads();

    for (int t = 0; t < T; t++) {
        int buf = t & 1;
        float4 pa0, pa1, pb0, pb1;
        if (t + 1 < T) {
            int k0 = (t + 1) << 4;
            pa0 = *(const float4*)(Ap + k0);
            pa1 = *(const float4*)(Ap + k0 + 4);
            pb0 = *(const float4*)(Wp + (size_t)k0 * N);
            pb1 = *(const float4*)(Wp + (size_t)k0 * N + 64);
        }
        #pragma unroll
        for (int ks = 0; ks < 16; ks += 8) {
            unsigned af[2][4], bf[8][2];
            #pragma unroll
            for (int mi = 0; mi < 2; mi++) {
                int m = wm + mi * 16 + grp;
                af[mi][0] = __float_as_uint(As[buf][m][ks + tg]);
                af[mi][1] = __float_as_uint(As[buf][m + 8][ks + tg]);
                af[mi][2] = __float_as_uint(As[buf][m][ks + tg + 4]);
                af[mi][3] = __float_as_uint(As[buf][m + 8][ks + tg + 4]);
            }
            #pragma unroll
            for (int ni = 0; ni < 8; ni++) {
                int n = wn + ni * 8 + grp;
                bf[ni][0] = __float_as_uint(Bs[buf][ks + tg][n]);
                bf[ni][1] = __float_as_uint(Bs[buf][ks + tg + 4][n]);
            }
            #pragma unroll
            for (int mi = 0; mi < 2; mi++)
                #pragma unroll
                for (int ni = 0; ni < 8; ni++)
                    mma8(acc[mi][ni], af[mi], bf[ni]);
        }
        if (t + 1 < T) {
            int nb = buf ^ 1;
            As[nb][ar][ac+0]=f2tf(pa0.x); As[nb][ar][ac+1]=f2tf(pa0.y);
            As[nb][ar][ac+2]=f2tf(pa0.z); As[nb][ar][ac+3]=f2tf(pa0.w);
            As[nb][ar][ac+4]=f2tf(pa1.x); As[nb][ar][ac+5]=f2tf(pa1.y);
            As[nb][ar][ac+6]=f2tf(pa1.z); As[nb][ar][ac+7]=f2tf(pa1.w);
            Bs[nb][br][bc+0]=f2tf(pb0.x); Bs[nb][br][bc+1]=f2tf(pb0.y);
            Bs[nb][br][bc+2]=f2tf(pb0.z); Bs[nb][br][bc+3]=f2tf(pb0.w);
            Bs[nb][br][bc+64]=f2tf(pb1.x); Bs[nb][br][bc+65]=f2tf(pb1.y);
            Bs[nb][br][bc+66]=f2tf(pb1.z); Bs[nb][br][bc+67]=f2tf(pb1.w);
        }
        __syncthreads();
    }

    #pragma unroll
    for (int mi = 0; mi < 2; mi++)
        #pragma unroll
        for (int ni = 0; ni < 8; ni++) {
            int row = bm + wm + mi * 16 + grp;
            int col = bn + wn + ni * 8 + tg * 2;
            float bs0 = bias[col], bs1 = bias[col + 1];
            float v0 = acc[mi][ni][0] + bs0, v1 = acc[mi][ni][1] + bs1;
            float v2 = acc[mi][ni][2] + bs0, v3 = acc[mi][ni][3] + bs1;
            if (GELU) {
                v0 = 0.5f * v0 * (1.0f + erff(v0 * 0.70710678118654752f));
                v1 = 0.5f * v1 * (1.0f + erff(v1 * 0.70710678118654752f));
                v2 = 0.5f * v2 * (1.0f + erff(v2 * 0.70710678118654752f));
                v3 = 0.5f * v3 * (1.0f + erff(v3 * 0.70710678118654752f));
            }
            float2* p0 = (float2*)(C + (size_t)row * N + col);
            float2* p1 = (float2*)(C + (size_t)(row + 8) * N + col);
            *p0 = make_float2(v0, v1);
            *p1 = make_float2(v2, v3);
        }
}

// ============================================================
// Scores (tf32): S[b,h,i,j] = (Q_h[i]·K_h[j])*SCALE (+prev) with anti-local
// mask. 128x128 tile, K=DK=64 (BK=16, 4 iters), double buffered.
// ============================================================
__global__ __launch_bounds__(256) void scores_tf32(const float* __restrict__ q,
                                                   const float* __restrict__ k,
                                                   float* __restrict__ scores,
                                                   int add_prev) {
    __shared__ float As[2][128][20];
    __shared__ float Bs[2][16][136];
    int bh = blockIdx.z;
    int b = bh >> 3, h = bh & 7;
    int i0 = blockIdx.y * 128, j0 = blockIdx.x * 128;
    int tid = threadIdx.x;
    int lane = tid & 31, w = tid >> 5;
    int grp = lane >> 2, tg = lane & 3;
    int wm = (w >> 1) * 32, wn = (w & 1) * 64;
    int ar = tid >> 1, ac = (tid & 1) * 8;
    int jj = tid >> 1, kc = (tid & 1) * 8;

    float acc[2][8][4];
    #pragma unroll
    for (int i = 0; i < 2; i++)
        #pragma unroll
        for (int j = 0; j < 8; j++)
            #pragma unroll
            for (int c = 0; c < 4; c++) acc[i][j][c] = 0.f;

    const float* qp = q + (size_t)b*L*D + (size_t)h*DK + (size_t)(i0 + ar)*D + ac;
    const float* kp = k + (size_t)b*L*D + (size_t)h*DK + (size_t)(j0 + jj)*D + kc;

    {   // stage tile 0
        float4 a0 = *(const float4*)(qp);
        float4 a1 = *(const float4*)(qp + 4);
        As[0][ar][ac+0]=f2tf(a0.x); As[0][ar][ac+1]=f2tf(a0.y);
        As[0][ar][ac+2]=f2tf(a0.z); As[0][ar][ac+3]=f2tf(a0.w);
        As[0][ar][ac+4]=f2tf(a1.x); As[0][ar][ac+5]=f2tf(a1.y);
        As[0][ar][ac+6]=f2tf(a1.z); As[0][ar][ac+7]=f2tf(a1.w);
        float4 k0v = *(const float4*)(kp);
        float4 k1v = *(const float4*)(kp + 4);
        Bs[0][kc+0][jj]=f2tf(k0v.x); Bs[0][kc+1][jj]=f2tf(k0v.y);
        Bs[0][kc+2][jj]=f2tf(k0v.z); Bs[0][kc+3][jj]=f2tf(k0v.w);
        Bs[0][kc+4][jj]=f2tf(k1v.x); Bs[0][kc+5][jj]=f2tf(k1v.y);
        Bs[0][kc+6][jj]=f2tf(k1v.z); Bs[0][kc+7][jj]=f2tf(k1v.w);
    }
    __syncthreads();

    #pragma unroll
    for (int t = 0; t < 4; t++) {
        int buf = t & 1;
        float4 pa0, pa1, pb0, pb1;
        if (t + 1 < 4) {
            int k0 = (t + 1) << 4;
            pa0 = *(const float4*)(qp + k0);
            pa1 = *(const float4*)(qp + k0 + 4);
            pb0 = *(const float4*)(kp + k0);
            pb1 = *(const float4*)(kp + k0 + 4);
        }
        #pragma unroll
        for (int ks = 0; ks < 16; ks += 8) {
            unsigned af[2][4], bf[8][2];
            #pragma unroll
            for (int mi = 0; mi < 2; mi++) {
                int m = wm + mi * 16 + grp;
                af[mi][0] = __float_as_uint(As[buf][m][ks + tg]);
                af[mi][1] = __float_as_uint(As[buf][m + 8][ks + tg]);
                af[mi][2] = __float_as_uint(As[buf][m][ks + tg + 4]);
                af[mi][3] = __float_as_uint(As[buf][m + 8][ks + tg + 4]);
            }
            #pragma unroll
            for (int ni = 0; ni < 8; ni++) {
                int n = wn + ni * 8 + grp;
                bf[ni][0] = __float_as_uint(Bs[buf][ks + tg][n]);
                bf[ni][1] = __float_as_uint(Bs[buf][ks + tg + 4][n]);
            }
            #pragma unroll
            for (int mi = 0; mi < 2; mi++)
                #pragma unroll
                for (int ni = 0; ni < 8; ni++)
                    mma8(acc[mi][ni], af[mi], bf[ni]);
        }
        if (t + 1 < 4) {
            int nb = buf ^ 1;
            As[nb][ar][ac+0]=f2tf(pa0.x); As[nb][ar][ac+1]=f2tf(pa0.y);
            As[nb][ar][ac+2]=f2tf(pa0.z); As[nb][ar][ac+3]=f2tf(pa0.w);
            As[nb][ar][ac+4]=f2tf(pa1.x); As[nb][ar][ac+5]=f2tf(pa1.y);
            As[nb][ar][ac+6]=f2tf(pa1.z); As[nb][ar][ac+7]=f2tf(pa1.w);
            Bs[nb][kc+0][jj]=f2tf(pb0.x); Bs[nb][kc+1][jj]=f2tf(pb0.y);
            Bs[nb][kc+2][jj]=f2tf(pb0.z); Bs[nb][kc+3][jj]=f2tf(pb0.w);
            Bs[nb][kc+4][jj]=f2tf(pb1.x); Bs[nb][kc+5][jj]=f2tf(pb1.y);
            Bs[nb][kc+6][jj]=f2tf(pb1.z); Bs[nb][kc+7][jj]=f2tf(pb1.w);
        }
        __syncthreads();
    }

    float* sb = scores + (size_t)bh * L * L;
    #pragma unroll
    for (int mi = 0; mi < 2; mi++)
        #pragma unroll
        for (int ni = 0; ni < 8; ni++) {
            int gi = i0 + wm + mi * 16 + grp;
            int gj = j0 + wn + ni * 8 + tg * 2;
            #pragma unroll
            for (int rr = 0; rr < 2; rr++) {
                int row = gi + rr * 8;
                float s0 = acc[mi][ni][rr * 2 + 0] * SCALE;
                float s1 = acc[mi][ni][rr * 2 + 1] * SCALE;
                float2* p = (float2*)(sb + (size_t)row * L + gj);
                if (add_prev) { float2 pv = *p; s0 += pv.x; s1 += pv.y; }
                int d0 = row - gj;     d0 = d0 < 0 ? -d0 : d0;
                int d1 = row - gj - 1; d1 = d1 < 0 ? -d1 : d1;
                if (d0 < HWIN) s0 = NEG;
                if (d1 < HWIN) s1 = NEG;
                *p = make_float2(s0, s1);
            }
        }
}

// ============================================================
// AV (tf32): O[b,i,h,:] = sum_m P[b,h,i,m] * V[b,m,h,:].
// 128x64 tile, K=L=1024 (BK=16, 64 iters), double buffered.
// 8 warps as 4x2, warptile 32x32.
// ============================================================
__global__ __launch_bounds__(256) void av_tf32(const float* __restrict__ attn,
                                               const float* __restrict__ v,
                                               float* __restrict__ out) {
    __shared__ float As[2][128][20];
    __shared__ float Bs[2][16][72];
    int bh = blockIdx.z;
    int b = bh >> 3, h = bh & 7;
    int i0 = blockIdx.x * 128;
    int tid = threadIdx.x;
    int lane = tid & 31, w = tid >> 5;
    int grp = lane >> 2, tg = lane & 3;
    int wm = (w >> 1) * 32, wn = (w & 1) * 32;
    int ar = tid >> 1, ac = (tid & 1) * 8;
    int br = tid >> 4, bc = (tid & 15) * 4;

    float acc[2][4][4];
    #pragma unroll
    for (int i = 0; i < 2; i++)
        #pragma unroll
        for (int j = 0; j < 4; j++)
            #pragma unroll
            for (int c = 0; c < 4; c++) acc[i][j][c] = 0.f;

    const float* Pp = attn + (size_t)bh*L*L + (size_t)(i0 + ar)*L + ac;
    const float* Vp = v + (size_t)b*L*D + (size_t)h*DK + (size_t)br*D + bc;

    {   // stage tile 0
        float4 a0 = *(const float4*)(Pp);
        float4 a1 = *(const float4*)(Pp + 4);
        As[0][ar][ac+0]=f2tf(a0.x); As[0][ar][ac+1]=f2tf(a0.y);
        As[0][ar][ac+2]=f2tf(a0.z); As[0][ar][ac+3]=f2tf(a0.w);
        As[0][ar][ac+4]=f2tf(a1.x); As[0][ar][ac+5]=f2tf(a1.y);
        As[0][ar][ac+6]=f2tf(a1.z); As[0][ar][ac+7]=f2tf(a1.w);
        float4 b0 = *(const float4*)(Vp);
        Bs[0][br][bc+0]=f2tf(b0.x); Bs[0][br][bc+1]=f2tf(b0.y);
        Bs[0][br][bc+2]=f2tf(b0.z); Bs[0][br][bc+3]=f2tf(b0.w);
    }
    __syncthreads();

    for (int t = 0; t < 64; t++) {
        int buf = t & 1;
        float4 pa0, pa1, pb0;
        if (t + 1 < 64) {
            int k0 = (t + 1) << 4;
            pa0 = *(const float4*)(Pp + k0);
            pa1 = *(const float4*)(Pp + k0 + 4);
            pb0 = *(const float4*)(Vp + (size_t)k0 * D);
        }
        #pragma unroll
        for (int ks = 0; ks < 16; ks += 8) {
            unsigned af[2][4], bf[4][2];
            #pragma unroll
            for (int mi = 0; mi < 2; mi++) {
                int m = wm + mi * 16 + grp;
                af[mi][0] = __float_as_uint(As[buf][m][ks + tg]);
                af[mi][1] = __float_as_uint(As[buf][m + 8][ks + tg]);
                af[mi][2] = __float_as_uint(As[buf][m][ks + tg + 4]);
                af[mi][3] = __float_as_uint(As[buf][m + 8][ks + tg + 4]);
            }
            #pragma unroll
            for (int ni = 0; ni < 4; ni++) {
                int n = wn + ni * 8 + grp;
                bf[ni][0] = __float_as_uint(Bs[buf][ks + tg][n]);
                bf[ni][1] = __float_as_uint(Bs[buf][ks + tg + 4][n]);
            }
            #pragma unroll
            for (int mi = 0; mi < 2; mi++)
                #pragma unroll
                for (int ni = 0; ni < 4; ni++)
                    mma8(acc[mi][ni], af[mi], bf[ni]);
        }
        if (t + 1 < 64) {
            int nb = buf ^ 1;
            As[nb][ar][ac+0]=f2tf(pa0.x); As[nb][ar][ac+1]=f2tf(pa0.y);
            As[nb][ar][ac+2]=f2tf(pa0.z); As[nb][ar][ac+3]=f2tf(pa0.w);
            As[nb][ar][ac+4]=f2tf(pa1.x); As[nb][ar][ac+5]=f2tf(pa1.y);
            As[nb][ar][ac+6]=f2tf(pa1.z); As[nb][ar][ac+7]=f2tf(pa1.w);
            Bs[nb][br][bc+0]=f2tf(pb0.x); Bs[nb][br][bc+1]=f2tf(pb0.y);
            Bs[nb][br][bc+2]=f2tf(pb0.z); Bs[nb][br][bc+3]=f2tf(pb0.w);
        }
        __syncthreads();
    }

    float* ob = out + (size_t)b*L*D + (size_t)h*DK;
    #pragma unroll
    for (int mi = 0; mi < 2; mi++)
        #pragma unroll
        for (int ni = 0; ni < 4; ni++) {
            int row = i0 + wm + mi * 16 + grp;
            int col = wn + ni * 8 + tg * 2;
            float2* p0 = (float2*)(ob + (size_t)row * D + col);
            float2* p1 = (float2*)(ob + (size_t)(row + 8) * D + col);
            *p0 = make_float2(acc[mi][ni][0], acc[mi][ni][1]);
            *p1 = make_float2(acc[mi][ni][2], acc[mi][ni][3]);
        }
}

// ============================================================
// Softmax over rows of length L=1024. One block (256 thr) per row.
// ============================================================
__global__ void softmax_kernel(const float* __restrict__ in, float* __restrict__ out) {
    int row = blockIdx.x;
    const float4* p = (const float4*)(in + (size_t)row * L);
    float4* o = (float4*)(out + (size_t)row * L);
    int tid = threadIdx.x;
    float4 v = p[tid];
    float m = fmaxf(fmaxf(v.x, v.y), fmaxf(v.z, v.w));
    __shared__ float red[8];
    #pragma unroll
    for (int off = 16; off; off >>= 1) m = fmaxf(m, __shfl_xor_sync(0xffffffffu, m, off));
    if ((tid & 31) == 0) red[tid >> 5] = m;
    __syncthreads();
    m = red[0];
    #pragma unroll
    for (int i = 1; i < 8; i++) m = fmaxf(m, red[i]);
    v.x = __expf(v.x - m); v.y = __expf(v.y - m);
    v.z = __expf(v.z - m); v.w = __expf(v.w - m);
    float s = v.x + v.y + v.z + v.w;
    #pragma unroll
    for (int off = 16; off; off >>= 1) s += __shfl_xor_sync(0xffffffffu, s, off);
    __syncthreads();
    if ((tid & 31) == 0) red[tid >> 5] = s;
    __syncthreads();
    s = red[0];
    #pragma unroll
    for (int i = 1; i < 8; i++) s += red[i];
    float inv = 1.0f / s;
    v.x *= inv; v.y *= inv; v.z *= inv; v.w *= inv;
    o[tid] = v;
}

// ============================================================
// out = LayerNorm(x + r) * gamma + beta. One block (128 thr) per row of 512.
// ============================================================
__global__ void addln_kernel(const float* __restrict__ x, const float* __restrict__ r,
                             const float* __restrict__ gam, const float* __restrict__ bet,
                             float* __restrict__ out) {
    int row = blockIdx.x;
    int tid = threadIdx.x;  // 128
    const float4* xp = (const float4*)(x + (size_t)row * D);
    const float4* rp = (const float4*)(r + (size_t)row * D);
    float4 a = xp[tid], b4 = rp[tid];
    float e0 = a.x + b4.x, e1 = a.y + b4.y, e2 = a.z + b4.z, e3 = a.w + b4.w;
    float s = e0 + e1 + e2 + e3;
    float qq = e0*e0 + e1*e1 + e2*e2 + e3*e3;
    __shared__ float rs[4], rq[4];
    #pragma unroll
    for (int off = 16; off; off >>= 1) {
        s  += __shfl_xor_sync(0xffffffffu, s, off);
        qq += __shfl_xor_sync(0xffffffffu, qq, off);
    }
    if ((tid & 31) == 0) { rs[tid >> 5] = s; rq[tid >> 5] = qq; }
    __syncthreads();
    s  = rs[0] + rs[1] + rs[2] + rs[3];
    qq = rq[0] + rq[1] + rq[2] + rq[3];
    float mean = s * (1.0f / D);
    float var  = qq * (1.0f / D) - mean * mean;
    float inv  = rsqrtf(var + EPS);
    float4 g4 = ((const float4*)gam)[tid];
    float4 bb = ((const float4*)bet)[tid];
    float4 ov;
    ov.x = (e0 - mean) * inv * g4.x + bb.x;
    ov.y = (e1 - mean) * inv * g4.y + bb.y;
    ov.z = (e2 - mean) * inv * g4.z + bb.z;
    ov.w = (e3 - mean) * inv * g4.w + bb.w;
    ((float4*)(out + (size_t)row * D))[tid] = ov;
}

// ============================================================
extern "C" void kernel_launch(void* const* d_in, const int* in_sizes, int n_in,
                              void* d_out, int out_size) {
    const float* src = (const float*)d_in[0];
    const float* Wq = (const float*)d_in[1];  const float* bq = (const float*)d_in[2];
    const float* Wk = (const float*)d_in[3];  const float* bk = (const float*)d_in[4];
    const float* Wv = (const float*)d_in[5];  const float* bv = (const float*)d_in[6];
    const float* Wo = (const float*)d_in[7];  const float* bo = (const float*)d_in[8];
    const float* W1 = (const float*)d_in[9];  const float* b1 = (const float*)d_in[10];
    const float* W2 = (const float*)d_in[11]; const float* b2 = (const float*)d_in[12];
    const float* ln1g = (const float*)d_in[13]; const float* ln1b = (const float*)d_in[14];
    const float* ln2g = (const float*)d_in[15]; const float* ln2b = (const float*)d_in[16];

    float *q, *k, *v, *x, *tmp, *ao, *ff, *sc, *pr;
    cudaGetSymbolAddress((void**)&q,  g_q);
    cudaGetSymbolAddress((void**)&k,  g_k);
    cudaGetSymbolAddress((void**)&v,  g_v);
    cudaGetSymbolAddress((void**)&x,  g_x);
    cudaGetSymbolAddress((void**)&tmp, g_tmp);
    cudaGetSymbolAddress((void**)&ao, g_ao);
    cudaGetSymbolAddress((void**)&ff, g_ff);
    cudaGetSymbolAddress((void**)&sc, g_scores);
    cudaGetSymbolAddress((void**)&pr, g_probs);

    dim3 gD(D/128, ROWS/128);     // 4 x 32
    dim3 gDF(DF/128, ROWS/128);   // 16 x 32
    dim3 gS(L/128, L/128, BH);    // 8 x 8 x 32
    dim3 gAV(L/128, 1, BH);       // 8 x 1 x 32

    const float* xin = src;
    for (int l = 0; l < NL; l++) {
        gemm_tf32<0><<<gD, 256>>>(xin, Wq + (size_t)l*D*D, bq + (size_t)l*D, q, ROWS, D, D);
        gemm_tf32<0><<<gD, 256>>>(xin, Wk + (size_t)l*D*D, bk + (size_t)l*D, k, ROWS, D, D);
        gemm_tf32<0><<<gD, 256>>>(xin, Wv + (size_t)l*D*D, bv + (size_t)l*D, v, ROWS, D, D);
        scores_tf32<<<gS, 256>>>(q, k, sc, l > 0 ? 1 : 0);
        softmax_kernel<<<BH*L, 256>>>(sc, pr);
        av_tf32<<<gAV, 256>>>(pr, v, ao);
        gemm_tf32<0><<<gD, 256>>>(ao, Wo + (size_t)l*D*D, bo + (size_t)l*D, tmp, ROWS, D, D);
        addln_kernel<<<ROWS, 128>>>(xin, tmp, ln1g + (size_t)l*D, ln1b + (size_t)l*D, x);
        gemm_tf32<1><<<gDF, 256>>>(x, W1 + (size_t)l*D*DF, b1 + (size_t)l*DF, ff, ROWS, DF, D);
        gemm_tf32<0><<<gD, 256>>>(ff, W2 + (size_t)l*DF*D, b2 + (size_t)l*D, tmp, ROWS, D, DF);
        float* lnout = (l == NL-1) ? (float*)d_out : x;
        addln_kernel<<<ROWS, 128>>>(x, tmp, ln2g + (size_t)l*D, ln2b + (size_t)l*D, lnout);
        xin = x;
    }
}

// round 6
// speedup vs baseline: 2.6756x; 1.1076x over previous
#include <cuda_runtime.h>
#include <math.h>

#define B 4
#define L 1024
#define D 512
#define H 8
#define DK 64
#define DF 2048
#define NL 2
#define HWIN 6
#define SCALE 0.125f
#define NEG -1e9f
#define EPS 1e-5f
#define ROWS (B*L)
#define BH (B*H)

// ---- scratch (device globals; no allocations allowed) ----
__device__ float g_q[B*L*D];
__device__ float g_k[B*L*D];
__device__ float g_v[B*L*D];
__device__ float g_x[B*L*D];
__device__ float g_tmp[B*L*D];
__device__ float g_ao[B*L*D];
__device__ float g_ff[B*L*DF];
__device__ float g_scores[(size_t)BH*L*L];   // masked pre-softmax scores (carried across layers)

// ============================================================
// tf32 helpers
// ============================================================
__device__ __forceinline__ float f2tf(float x) {
    unsigned u; asm("cvt.rna.tf32.f32 %0, %1;" : "=r"(u) : "f"(x));
    return __uint_as_float(u);
}
__device__ __forceinline__ void mma8(float* d, const unsigned* a, const unsigned* b) {
    asm volatile("mma.sync.aligned.m16n8k8.row.col.f32.tf32.tf32.f32 "
                 "{%0,%1,%2,%3}, {%4,%5,%6,%7}, {%8,%9}, {%0,%1,%2,%3};\n"
                 : "+f"(d[0]), "+f"(d[1]), "+f"(d[2]), "+f"(d[3])
                 : "r"(a[0]), "r"(a[1]), "r"(a[2]), "r"(a[3]),
                   "r"(b[0]), "r"(b[1]));
}

// ============================================================
// Shared GEMM body: C[.,N] tile (bm,bn) = A[.,K] @ W[K,N] + bias, opt GELU.
// 128x128 tile, BK=16, 256 thr (8 warps 4x2, warptile 32x64), reg-prefetch
// double buffering.
// ============================================================
template<int GELU>
__device__ __forceinline__ void gemm_body(const float* __restrict__ A,
                                          const float* __restrict__ W,
                                          const float* __restrict__ bias,
                                          float* __restrict__ C,
                                          int N, int K, int bm, int bn,
                                          float (&As)[2][128][20],
                                          float (&Bs)[2][16][136]) {
    int tid = threadIdx.x;
    int lane = tid & 31, w = tid >> 5;
    int grp = lane >> 2, tg = lane & 3;
    int wm = (w >> 1) * 32, wn = (w & 1) * 64;
    int ar = tid >> 1, ac = (tid & 1) * 8;
    int br = tid >> 4, bc = (tid & 15) * 4;

    float acc[2][8][4];
    #pragma unroll
    for (int i = 0; i < 2; i++)
        #pragma unroll
        for (int j = 0; j < 8; j++)
            #pragma unroll
            for (int c = 0; c < 4; c++) acc[i][j][c] = 0.f;

    const float* Ap = A + (size_t)(bm + ar) * K + ac;
    const float* Wp = W + (size_t)br * N + bn + bc;
    int T = K >> 4;

    {   // stage tile 0
        float4 a0 = *(const float4*)(Ap);
        float4 a1 = *(const float4*)(Ap + 4);
        As[0][ar][ac+0]=f2tf(a0.x); As[0][ar][ac+1]=f2tf(a0.y);
        As[0][ar][ac+2]=f2tf(a0.z); As[0][ar][ac+3]=f2tf(a0.w);
        As[0][ar][ac+4]=f2tf(a1.x); As[0][ar][ac+5]=f2tf(a1.y);
        As[0][ar][ac+6]=f2tf(a1.z); As[0][ar][ac+7]=f2tf(a1.w);
        float4 b0 = *(const float4*)(Wp);
        float4 b1 = *(const float4*)(Wp + 64);
        Bs[0][br][bc+0]=f2tf(b0.x); Bs[0][br][bc+1]=f2tf(b0.y);
        Bs[0][br][bc+2]=f2tf(b0.z); Bs[0][br][bc+3]=f2tf(b0.w);
        Bs[0][br][bc+64]=f2tf(b1.x); Bs[0][br][bc+65]=f2tf(b1.y);
        Bs[0][br][bc+66]=f2tf(b1.z); Bs[0][br][bc+67]=f2tf(b1.w);
    }
    __syncthreads();

    for (int t = 0; t < T; t++) {
        int buf = t & 1;
        float4 pa0, pa1, pb0, pb1;
        if (t + 1 < T) {
            int k0 = (t + 1) << 4;
            pa0 = *(const float4*)(Ap + k0);
            pa1 = *(const float4*)(Ap + k0 + 4);
            pb0 = *(const float4*)(Wp + (size_t)k0 * N);
            pb1 = *(const float4*)(Wp + (size_t)k0 * N + 64);
        }
        #pragma unroll
        for (int ks = 0; ks < 16; ks += 8) {
            unsigned af[2][4], bf[8][2];
            #pragma unroll
            for (int mi = 0; mi < 2; mi++) {
                int m = wm + mi * 16 + grp;
                af[mi][0] = __float_as_uint(As[buf][m][ks + tg]);
                af[mi][1] = __float_as_uint(As[buf][m + 8][ks + tg]);
                af[mi][2] = __float_as_uint(As[buf][m][ks + tg + 4]);
                af[mi][3] = __float_as_uint(As[buf][m + 8][ks + tg + 4]);
            }
            #pragma unroll
            for (int ni = 0; ni < 8; ni++) {
                int n = wn + ni * 8 + grp;
                bf[ni][0] = __float_as_uint(Bs[buf][ks + tg][n]);
                bf[ni][1] = __float_as_uint(Bs[buf][ks + tg + 4][n]);
            }
            #pragma unroll
            for (int mi = 0; mi < 2; mi++)
                #pragma unroll
                for (int ni = 0; ni < 8; ni++)
                    mma8(acc[mi][ni], af[mi], bf[ni]);
        }
        if (t + 1 < T) {
            int nb = buf ^ 1;
            As[nb][ar][ac+0]=f2tf(pa0.x); As[nb][ar][ac+1]=f2tf(pa0.y);
            As[nb][ar][ac+2]=f2tf(pa0.z); As[nb][ar][ac+3]=f2tf(pa0.w);
            As[nb][ar][ac+4]=f2tf(pa1.x); As[nb][ar][ac+5]=f2tf(pa1.y);
            As[nb][ar][ac+6]=f2tf(pa1.z); As[nb][ar][ac+7]=f2tf(pa1.w);
            Bs[nb][br][bc+0]=f2tf(pb0.x); Bs[nb][br][bc+1]=f2tf(pb0.y);
            Bs[nb][br][bc+2]=f2tf(pb0.z); Bs[nb][br][bc+3]=f2tf(pb0.w);
            Bs[nb][br][bc+64]=f2tf(pb1.x); Bs[nb][br][bc+65]=f2tf(pb1.y);
            Bs[nb][br][bc+66]=f2tf(pb1.z); Bs[nb][br][bc+67]=f2tf(pb1.w);
        }
        __syncthreads();
    }

    #pragma unroll
    for (int mi = 0; mi < 2; mi++)
        #pragma unroll
        for (int ni = 0; ni < 8; ni++) {
            int row = bm + wm + mi * 16 + grp;
            int col = bn + wn + ni * 8 + tg * 2;
            float bs0 = bias[col], bs1 = bias[col + 1];
            float v0 = acc[mi][ni][0] + bs0, v1 = acc[mi][ni][1] + bs1;
            float v2 = acc[mi][ni][2] + bs0, v3 = acc[mi][ni][3] + bs1;
            if (GELU) {
                v0 = 0.5f * v0 * (1.0f + erff(v0 * 0.70710678118654752f));
                v1 = 0.5f * v1 * (1.0f + erff(v1 * 0.70710678118654752f));
                v2 = 0.5f * v2 * (1.0f + erff(v2 * 0.70710678118654752f));
                v3 = 0.5f * v3 * (1.0f + erff(v3 * 0.70710678118654752f));
            }
            float2* p0 = (float2*)(C + (size_t)row * N + col);
            float2* p1 = (float2*)(C + (size_t)(row + 8) * N + col);
            *p0 = make_float2(v0, v1);
            *p1 = make_float2(v2, v3);
        }
}

template<int GELU>
__global__ __launch_bounds__(256) void gemm_tf32(const float* __restrict__ A,
                                                 const float* __restrict__ W,
                                                 const float* __restrict__ bias,
                                                 float* __restrict__ C,
                                                 int N, int K) {
    __shared__ float As[2][128][20];
    __shared__ float Bs[2][16][136];
    gemm_body<GELU>(A, W, bias, C, N, K, blockIdx.y * 128, blockIdx.x * 128, As, Bs);
}

// fused QKV: blockIdx.x in [0,12): sel = bx>>2 picks {q,k,v}, (bx&3) n-tile.
__global__ __launch_bounds__(256) void qkv_gemm(const float* __restrict__ A,
        const float* __restrict__ Wq, const float* __restrict__ bq,
        const float* __restrict__ Wk, const float* __restrict__ bk,
        const float* __restrict__ Wv, const float* __restrict__ bv,
        float* __restrict__ q, float* __restrict__ k, float* __restrict__ v) {
    __shared__ float As[2][128][20];
    __shared__ float Bs[2][16][136];
    int sel = blockIdx.x >> 2;
    const float* W = sel == 0 ? Wq : (sel == 1 ? Wk : Wv);
    const float* bias = sel == 0 ? bq : (sel == 1 ? bk : bv);
    float* C = sel == 0 ? q : (sel == 1 ? k : v);
    gemm_body<0>(A, W, bias, C, D, D, blockIdx.y * 128, (blockIdx.x & 3) * 128, As, Bs);
}

// ============================================================
// Fused attention: per (bh, 128-row i-strip) block does:
//   pass1: S = QK^T*SCALE (+prev), mask, write scores, track row-max
//   pass2: re-read scores (L2-hot), p = exp(s-m), row-sum, O = P@V, normalize
// ============================================================
__global__ __launch_bounds__(256) void attn_fused(const float* __restrict__ q,
                                                  const float* __restrict__ k,
                                                  const float* __restrict__ v,
                                                  float* __restrict__ scores,
                                                  float* __restrict__ ao,
                                                  int add_prev) {
    __shared__ float m_part[2][128];
    __shared__ float m_row[128];
    __shared__ float s_red[256];
    __shared__ float inv_row[128];
    __shared__ float u[8704];   // pass1: Qs[128][68] then Bs[2][16][136]; pass2: Ps+Vs

    int bh = blockIdx.y;
    int b = bh >> 3, h = bh & 7;
    int i0 = blockIdx.x * 128;
    int tid = threadIdx.x, lane = tid & 31, w = tid >> 5;
    int grp = lane >> 2, tg = lane & 3;
    int wm = (w >> 1) * 32, wn = (w & 1) * 64;

    // ---------------- pass 1 ----------------
    {   // stage Q strip [128][64] -> u (row stride 68), tf32
        const float4* qsrc = (const float4*)(q + ((size_t)b * L + i0) * D + h * DK);
        #pragma unroll
        for (int it = 0; it < 8; it++) {
            int idx = tid + it * 256;          // 0..2047 float4s
            int row = idx >> 4, c4 = idx & 15;
            float4 t = qsrc[(size_t)row * (D / 4) + c4];
            float* dst = &u[row * 68 + c4 * 4];
            dst[0] = f2tf(t.x); dst[1] = f2tf(t.y); dst[2] = f2tf(t.z); dst[3] = f2tf(t.w);
        }
    }
    __syncthreads();
    unsigned af[8][2][4];                      // Q fragments live in regs all of pass1
    #pragma unroll
    for (int ks = 0; ks < 8; ks++)
        #pragma unroll
        for (int mi = 0; mi < 2; mi++) {
            int m = wm + mi * 16 + grp;
            af[ks][mi][0] = __float_as_uint(u[m * 68 + ks * 8 + tg]);
            af[ks][mi][1] = __float_as_uint(u[(m + 8) * 68 + ks * 8 + tg]);
            af[ks][mi][2] = __float_as_uint(u[m * 68 + ks * 8 + tg + 4]);
            af[ks][mi][3] = __float_as_uint(u[(m + 8) * 68 + ks * 8 + tg + 4]);
        }
    __syncthreads();

    float (*Bs)[16][136] = (float (*)[16][136])u;
    float rm[4] = {-3.4e38f, -3.4e38f, -3.4e38f, -3.4e38f};
    float acc[2][8][4];
    #pragma unroll
    for (int i = 0; i < 2; i++)
        #pragma unroll
        for (int j = 0; j < 8; j++)
            #pragma unroll
            for (int c = 0; c < 4; c++) acc[i][j][c] = 0.f;

    const float* kbase = k + (size_t)b * L * D + h * DK;
    float* sb = scores + (size_t)bh * L * L;
    int jj = tid >> 1, kc = (tid & 1) * 8;

    float4 ca, cb;
    {   // prefetch chunk (jt=0,c=0)
        const float* src = kbase + (size_t)jj * D + kc;
        ca = *(const float4*)(src); cb = *(const float4*)(src + 4);
        Bs[0][kc+0][jj]=f2tf(ca.x); Bs[0][kc+1][jj]=f2tf(ca.y);
        Bs[0][kc+2][jj]=f2tf(ca.z); Bs[0][kc+3][jj]=f2tf(ca.w);
        Bs[0][kc+4][jj]=f2tf(cb.x); Bs[0][kc+5][jj]=f2tf(cb.y);
        Bs[0][kc+6][jj]=f2tf(cb.z); Bs[0][kc+7][jj]=f2tf(cb.w);
    }
    __syncthreads();

    for (int jt = 0; jt < 8; jt++) {
        #pragma unroll
        for (int c = 0; c < 4; c++) {
            int buf = c & 1;
            int nch = jt * 4 + c + 1;
            float4 na, nb;
            if (nch < 32) {
                const float* src = kbase + (size_t)((nch >> 2) * 128 + jj) * D + (nch & 3) * 16 + kc;
                na = *(const float4*)(src); nb = *(const float4*)(src + 4);
            }
            #pragma unroll
            for (int ksl = 0; ksl < 2; ksl++) {
                unsigned bf[8][2];
                #pragma unroll
                for (int ni = 0; ni < 8; ni++) {
                    int n = wn + ni * 8 + grp;
                    bf[ni][0] = __float_as_uint(Bs[buf][ksl*8 + tg][n]);
                    bf[ni][1] = __float_as_uint(Bs[buf][ksl*8 + tg + 4][n]);
                }
                #pragma unroll
                for (int mi = 0; mi < 2; mi++)
                    #pragma unroll
                    for (int ni = 0; ni < 8; ni++)
                        mma8(acc[mi][ni], af[c*2 + ksl][mi], bf[ni]);
            }
            if (c == 3) {   // j-tile epilogue
                #pragma unroll
                for (int mi = 0; mi < 2; mi++)
                    #pragma unroll
                    for (int ni = 0; ni < 8; ni++) {
                        int gi = i0 + wm + mi * 16 + grp;
                        int gj = jt * 128 + wn + ni * 8 + tg * 2;
                        #pragma unroll
                        for (int rr = 0; rr < 2; rr++) {
                            int row = gi + rr * 8;
                            float s0 = acc[mi][ni][rr*2 + 0] * SCALE;
                            float s1 = acc[mi][ni][rr*2 + 1] * SCALE;
                            float2* p = (float2*)(sb + (size_t)row * L + gj);
                            if (add_prev) { float2 pv = *p; s0 += pv.x; s1 += pv.y; }
                            int d0 = row - gj;     d0 = d0 < 0 ? -d0 : d0;
                            int d1 = row - gj - 1; d1 = d1 < 0 ? -d1 : d1;
                            if (d0 < HWIN) s0 = NEG;
                            if (d1 < HWIN) s1 = NEG;
                            *p = make_float2(s0, s1);
                            rm[mi*2 + rr] = fmaxf(rm[mi*2 + rr], fmaxf(s0, s1));
                            acc[mi][ni][rr*2 + 0] = 0.f;
                            acc[mi][ni][rr*2 + 1] = 0.f;
                        }
                    }
            }
            if (nch < 32) {
                int nb2 = buf ^ 1;
                Bs[nb2][kc+0][jj]=f2tf(na.x); Bs[nb2][kc+1][jj]=f2tf(na.y);
                Bs[nb2][kc+2][jj]=f2tf(na.z); Bs[nb2][kc+3][jj]=f2tf(na.w);
                Bs[nb2][kc+4][jj]=f2tf(nb.x); Bs[nb2][kc+5][jj]=f2tf(nb.y);
                Bs[nb2][kc+6][jj]=f2tf(nb.z); Bs[nb2][kc+7][jj]=f2tf(nb.w);
            }
            __syncthreads();
        }
    }

    // reduce row max: over quad (tg) lanes, then across the 2 warps per row set
    #pragma unroll
    for (int mi = 0; mi < 2; mi++)
        #pragma unroll
        for (int rr = 0; rr < 2; rr++) {
            float vv = rm[mi*2 + rr];
            vv = fmaxf(vv, __shfl_xor_sync(0xffffffffu, vv, 1));
            vv = fmaxf(vv, __shfl_xor_sync(0xffffffffu, vv, 2));
            if (tg == 0) m_part[w & 1][wm + mi*16 + grp + rr*8] = vv;
        }
    __syncthreads();
    if (tid < 128) m_row[tid] = fmaxf(m_part[0][tid], m_part[1][tid]);
    __syncthreads();

    // ---------------- pass 2: O = softmax(S) @ V ----------------
    int ar = tid >> 1, ac = (tid & 1) * 8;
    int br = tid >> 4, bc = (tid & 15) * 4;
    int wn2 = (w & 1) * 32;
    float (*Ps)[128][20] = (float (*)[128][20])u;
    float (*Vs)[16][72]  = (float (*)[16][72])(u + 5120);
    const float* Sp = sb + (size_t)(i0 + ar) * L + ac;
    const float* Vp = v + (size_t)b * L * D + h * DK + (size_t)br * D + bc;
    float mrow = m_row[ar];
    float sum_part = 0.f;
    float acc2[2][4][4];
    #pragma unroll
    for (int i = 0; i < 2; i++)
        #pragma unroll
        for (int j = 0; j < 4; j++)
            #pragma unroll
            for (int c = 0; c < 4; c++) acc2[i][j][c] = 0.f;

    {   // stage chunk 0
        float4 s0 = *(const float4*)(Sp), s1 = *(const float4*)(Sp + 4);
        float4 vv = *(const float4*)(Vp);
        float p0=__expf(s0.x-mrow), p1=__expf(s0.y-mrow), p2=__expf(s0.z-mrow), p3=__expf(s0.w-mrow);
        float p4=__expf(s1.x-mrow), p5=__expf(s1.y-mrow), p6=__expf(s1.z-mrow), p7=__expf(s1.w-mrow);
        sum_part += p0+p1+p2+p3+p4+p5+p6+p7;
        float* pd = &Ps[0][ar][ac];
        pd[0]=f2tf(p0); pd[1]=f2tf(p1); pd[2]=f2tf(p2); pd[3]=f2tf(p3);
        pd[4]=f2tf(p4); pd[5]=f2tf(p5); pd[6]=f2tf(p6); pd[7]=f2tf(p7);
        Vs[0][br][bc+0]=f2tf(vv.x); Vs[0][br][bc+1]=f2tf(vv.y);
        Vs[0][br][bc+2]=f2tf(vv.z); Vs[0][br][bc+3]=f2tf(vv.w);
    }
    __syncthreads();

    for (int t = 0; t < 64; t++) {
        int buf = t & 1;
        float4 ns0, ns1, nv;
        if (t + 1 < 64) {
            ns0 = *(const float4*)(Sp + (t+1)*16);
            ns1 = *(const float4*)(Sp + (t+1)*16 + 4);
            nv  = *(const float4*)(Vp + (size_t)(t+1) * 16 * D);
        }
        #pragma unroll
        for (int ksl = 0; ksl < 2; ksl++) {
            unsigned a2[2][4], b2[4][2];
            #pragma unroll
            for (int mi = 0; mi < 2; mi++) {
                int m = wm + mi * 16 + grp;
                a2[mi][0] = __float_as_uint(Ps[buf][m][ksl*8 + tg]);
                a2[mi][1] = __float_as_uint(Ps[buf][m + 8][ksl*8 + tg]);
                a2[mi][2] = __float_as_uint(Ps[buf][m][ksl*8 + tg + 4]);
                a2[mi][3] = __float_as_uint(Ps[buf][m + 8][ksl*8 + tg + 4]);
            }
            #pragma unroll
            for (int ni = 0; ni < 4; ni++) {
                int n = wn2 + ni * 8 + grp;
                b2[ni][0] = __float_as_uint(Vs[buf][ksl*8 + tg][n]);
                b2[ni][1] = __float_as_uint(Vs[buf][ksl*8 + tg + 4][n]);
            }
            #pragma unroll
            for (int mi = 0; mi < 2; mi++)
                #pragma unroll
                for (int ni = 0; ni < 4; ni++)
                    mma8(acc2[mi][ni], a2[mi], b2[ni]);
        }
        if (t + 1 < 64) {
            int nb2 = buf ^ 1;
            float p0=__expf(ns0.x-mrow), p1=__expf(ns0.y-mrow), p2=__expf(ns0.z-mrow), p3=__expf(ns0.w-mrow);
            float p4=__expf(ns1.x-mrow), p5=__expf(ns1.y-mrow), p6=__expf(ns1.z-mrow), p7=__expf(ns1.w-mrow);
            sum_part += p0+p1+p2+p3+p4+p5+p6+p7;
            float* pd = &Ps[nb2][ar][ac];
            pd[0]=f2tf(p0); pd[1]=f2tf(p1); pd[2]=f2tf(p2); pd[3]=f2tf(p3);
            pd[4]=f2tf(p4); pd[5]=f2tf(p5); pd[6]=f2tf(p6); pd[7]=f2tf(p7);
            Vs[nb2][br][bc+0]=f2tf(nv.x); Vs[nb2][br][bc+1]=f2tf(nv.y);
            Vs[nb2][br][bc+2]=f2tf(nv.z); Vs[nb2][br][bc+3]=f2tf(nv.w);
        }
        __syncthreads();
    }

    s_red[tid] = sum_part;
    __syncthreads();
    if (tid < 128) inv_row[tid] = 1.0f / (s_red[2*tid] + s_red[2*tid + 1]);
    __syncthreads();

    float* ob = ao + (size_t)b * L * D + h * DK;
    #pragma unroll
    for (int mi = 0; mi < 2; mi++)
        #pragma unroll
        for (int ni = 0; ni < 4; ni++) {
            int rl = wm + mi * 16 + grp;
            int col = wn2 + ni * 8 + tg * 2;
            float iv0 = inv_row[rl], iv1 = inv_row[rl + 8];
            float2* p0 = (float2*)(ob + (size_t)(i0 + rl) * D + col);
            float2* p1 = (float2*)(ob + (size_t)(i0 + rl + 8) * D + col);
            *p0 = make_float2(acc2[mi][ni][0] * iv0, acc2[mi][ni][1] * iv0);
            *p1 = make_float2(acc2[mi][ni][2] * iv1, acc2[mi][ni][3] * iv1);
        }
}

// ============================================================
// out = LayerNorm(x + r) * gamma + beta. One block (128 thr) per row of 512.
// ============================================================
__global__ void addln_kernel(const float* __restrict__ x, const float* __restrict__ r,
                             const float* __restrict__ gam, const float* __restrict__ bet,
                             float* __restrict__ out) {
    int row = blockIdx.x;
    int tid = threadIdx.x;  // 128
    const float4* xp = (const float4*)(x + (size_t)row * D);
    const float4* rp = (const float4*)(r + (size_t)row * D);
    float4 a = xp[tid], b4 = rp[tid];
    float e0 = a.x + b4.x, e1 = a.y + b4.y, e2 = a.z + b4.z, e3 = a.w + b4.w;
    float s = e0 + e1 + e2 + e3;
    float qq = e0*e0 + e1*e1 + e2*e2 + e3*e3;
    __shared__ float rs[4], rq[4];
    #pragma unroll
    for (int off = 16; off; off >>= 1) {
        s  += __shfl_xor_sync(0xffffffffu, s, off);
        qq += __shfl_xor_sync(0xffffffffu, qq, off);
    }
    if ((tid & 31) == 0) { rs[tid >> 5] = s; rq[tid >> 5] = qq; }
    __syncthreads();
    s  = rs[0] + rs[1] + rs[2] + rs[3];
    qq = rq[0] + rq[1] + rq[2] + rq[3];
    float mean = s * (1.0f / D);
    float var  = qq * (1.0f / D) - mean * mean;
    float inv  = rsqrtf(var + EPS);
    float4 g4 = ((const float4*)gam)[tid];
    float4 bb = ((const float4*)bet)[tid];
    float4 ov;
    ov.x = (e0 - mean) * inv * g4.x + bb.x;
    ov.y = (e1 - mean) * inv * g4.y + bb.y;
    ov.z = (e2 - mean) * inv * g4.z + bb.z;
    ov.w = (e3 - mean) * inv * g4.w + bb.w;
    ((float4*)(out + (size_t)row * D))[tid] = ov;
}

// ============================================================
extern "C" void kernel_launch(void* const* d_in, const int* in_sizes, int n_in,
                              void* d_out, int out_size) {
    const float* src = (const float*)d_in[0];
    const float* Wq = (const float*)d_in[1];  const float* bq = (const float*)d_in[2];
    const float* Wk = (const float*)d_in[3];  const float* bk = (const float*)d_in[4];
    const float* Wv = (const float*)d_in[5];  const float* bv = (const float*)d_in[6];
    const float* Wo = (const float*)d_in[7];  const float* bo = (const float*)d_in[8];
    const float* W1 = (const float*)d_in[9];  const float* b1 = (const float*)d_in[10];
    const float* W2 = (const float*)d_in[11]; const float* b2 = (const float*)d_in[12];
    const float* ln1g = (const float*)d_in[13]; const float* ln1b = (const float*)d_in[14];
    const float* ln2g = (const float*)d_in[15]; const float* ln2b = (const float*)d_in[16];

    float *q, *k, *v, *x, *tmp, *ao, *ff, *sc;
    cudaGetSymbolAddress((void**)&q,  g_q);
    cudaGetSymbolAddress((void**)&k,  g_k);
    cudaGetSymbolAddress((void**)&v,  g_v);
    cudaGetSymbolAddress((void**)&x,  g_x);
    cudaGetSymbolAddress((void**)&tmp, g_tmp);
    cudaGetSymbolAddress((void**)&ao, g_ao);
    cudaGetSymbolAddress((void**)&ff, g_ff);
    cudaGetSymbolAddress((void**)&sc, g_scores);

    dim3 gD(D/128, ROWS/128);     // 4 x 32
    dim3 gDF(DF/128, ROWS/128);   // 16 x 32
    dim3 gQKV(12, ROWS/128);      // 12 x 32
    dim3 gA(L/128, BH);           // 8 x 32

    const float* xin = src;
    for (int l = 0; l < NL; l++) {
        qkv_gemm<<<gQKV, 256>>>(xin,
            Wq + (size_t)l*D*D, bq + (size_t)l*D,
            Wk + (size_t)l*D*D, bk + (size_t)l*D,
            Wv + (size_t)l*D*D, bv + (size_t)l*D, q, k, v);
        attn_fused<<<gA, 256>>>(q, k, v, sc, ao, l > 0 ? 1 : 0);
        gemm_tf32<0><<<gD, 256>>>(ao, Wo + (size_t)l*D*D, bo + (size_t)l*D, tmp, D, D);
        addln_kernel<<<ROWS, 128>>>(xin, tmp, ln1g + (size_t)l*D, ln1b + (size_t)l*D, x);
        gemm_tf32<1><<<gDF, 256>>>(x, W1 + (size_t)l*D*DF, b1 + (size_t)l*DF, ff, DF, D);
        gemm_tf32<0><<<gD, 256>>>(ff, W2 + (size_t)l*DF*D, b2 + (size_t)l*D, tmp, D, DF);
        float* lnout = (l == NL-1) ? (float*)d_out : x;
        addln_kernel<<<ROWS, 128>>>(x, tmp, ln2g + (size_t)l*D, ln2b + (size_t)l*D, lnout);
        xin = x;
    }
}

// round 7
// speedup vs baseline: 2.7977x; 1.0457x over previous
#include <cuda_runtime.h>
#include <math.h>

#define B 4
#define L 1024
#define D 512
#define H 8
#define DK 64
#define DF 2048
#define NL 2
#define HWIN 6
#define SCALE 0.125f
#define NEG -1e9f
#define EPS 1e-5f
#define ROWS (B*L)
#define BH (B*H)

// ---- scratch (device globals; no allocations allowed) ----
__device__ float g_q[B*L*D];
__device__ float g_k[B*L*D];
__device__ float g_v[B*L*D];
__device__ float g_x[B*L*D];
__device__ float g_tmp[B*L*D];
__device__ float g_ao[B*L*D];
__device__ float g_ff[B*L*DF];
__device__ float g_scores[(size_t)BH*L*L];   // masked pre-softmax scores (carried across layers)

// ============================================================
// helpers: raw-bit tf32 (HW truncates low mantissa), mma, cp.async
// ============================================================
__device__ __forceinline__ float f2tf(float x) { return x; }  // truncation via mma HW
__device__ __forceinline__ void mma8(float* d, const unsigned* a, const unsigned* b) {
    asm volatile("mma.sync.aligned.m16n8k8.row.col.f32.tf32.tf32.f32 "
                 "{%0,%1,%2,%3}, {%4,%5,%6,%7}, {%8,%9}, {%0,%1,%2,%3};\n"
                 : "+f"(d[0]), "+f"(d[1]), "+f"(d[2]), "+f"(d[3])
                 : "r"(a[0]), "r"(a[1]), "r"(a[2]), "r"(a[3]),
                   "r"(b[0]), "r"(b[1]));
}
__device__ __forceinline__ void cpa16(float* s, const float* g) {
    unsigned a = (unsigned)__cvta_generic_to_shared(s);
    asm volatile("cp.async.cg.shared.global [%0], [%1], 16;\n" :: "r"(a), "l"(g));
}
#define CP_COMMIT() asm volatile("cp.async.commit_group;\n")
#define CP_WAIT1()  asm volatile("cp.async.wait_group 1;\n")

// dynamic smem layout for GEMM: 3 stages
//   A stage: 128 rows x stride 20 floats (16 data + 4 pad) = 2560 floats
//   B stage: 16 rows x stride 136 floats (128 data + 8 pad) = 2176 floats
#define AST 2560
#define BST 2176
#define GEMM_SMEM (3*(AST+BST)*4)   // 56832 bytes

// ============================================================
// GEMM body: C[.,N] tile (bm,bn) = A[.,K] @ W[K,N] + bias, opt GELU.
// 128x128 tile, BK=16, 256 thr (8 warps 4x2, warptile 32x64),
// cp.async 3-stage pipeline, raw-bit tf32 mma. M%128==0, N%128==0, K%16==0.
// ============================================================
template<int GELU>
__device__ __forceinline__ void gemm_body(const float* __restrict__ A,
                                          const float* __restrict__ W,
                                          const float* __restrict__ bias,
                                          float* __restrict__ C,
                                          int N, int K, int bm, int bn,
                                          float* smA, float* smB) {
    int tid = threadIdx.x;
    int lane = tid & 31, w = tid >> 5;
    int grp = lane >> 2, tg = lane & 3;
    int wm = (w >> 1) * 32, wn = (w & 1) * 64;
    int ar = tid >> 1, ac = (tid & 1) * 8;
    int br = tid >> 4, bc = (tid & 15) * 8;

    float acc[2][8][4];
    #pragma unroll
    for (int i = 0; i < 2; i++)
        #pragma unroll
        for (int j = 0; j < 8; j++)
            #pragma unroll
            for (int c = 0; c < 4; c++) acc[i][j][c] = 0.f;

    const float* Ap = A + (size_t)(bm + ar) * K + ac;
    const float* Wp = W + (size_t)br * N + bn + bc;
    int T = K >> 4;

    auto issue = [&](int t) {
        int s = t % 3;
        const float* a = Ap + (t << 4);
        cpa16(&smA[s*AST + ar*20 + ac],     a);
        cpa16(&smA[s*AST + ar*20 + ac + 4], a + 4);
        const float* bsrc = Wp + (size_t)(t << 4) * N;
        cpa16(&smB[s*BST + br*136 + bc],     bsrc);
        cpa16(&smB[s*BST + br*136 + bc + 4], bsrc + 4);
    };

    if (0 < T) issue(0);
    CP_COMMIT();
    if (1 < T) issue(1);
    CP_COMMIT();

    for (int t = 0; t < T; t++) {
        CP_WAIT1();
        __syncthreads();
        if (t + 2 < T) issue(t + 2);
        CP_COMMIT();
        const float* As = &smA[(t % 3) * AST];
        const float* Bs = &smB[(t % 3) * BST];
        #pragma unroll
        for (int ks = 0; ks < 16; ks += 8) {
            unsigned af[2][4], bf[8][2];
            #pragma unroll
            for (int mi = 0; mi < 2; mi++) {
                int m = wm + mi * 16 + grp;
                af[mi][0] = __float_as_uint(As[m*20 + ks + tg]);
                af[mi][1] = __float_as_uint(As[(m+8)*20 + ks + tg]);
                af[mi][2] = __float_as_uint(As[m*20 + ks + tg + 4]);
                af[mi][3] = __float_as_uint(As[(m+8)*20 + ks + tg + 4]);
            }
            #pragma unroll
            for (int ni = 0; ni < 8; ni++) {
                int n = wn + ni * 8 + grp;
                bf[ni][0] = __float_as_uint(Bs[(ks+tg)*136 + n]);
                bf[ni][1] = __float_as_uint(Bs[(ks+tg+4)*136 + n]);
            }
            #pragma unroll
            for (int mi = 0; mi < 2; mi++)
                #pragma unroll
                for (int ni = 0; ni < 8; ni++)
                    mma8(acc[mi][ni], af[mi], bf[ni]);
        }
        __syncthreads();
    }

    #pragma unroll
    for (int mi = 0; mi < 2; mi++)
        #pragma unroll
        for (int ni = 0; ni < 8; ni++) {
            int row = bm + wm + mi * 16 + grp;
            int col = bn + wn + ni * 8 + tg * 2;
            float bs0 = bias[col], bs1 = bias[col + 1];
            float v0 = acc[mi][ni][0] + bs0, v1 = acc[mi][ni][1] + bs1;
            float v2 = acc[mi][ni][2] + bs0, v3 = acc[mi][ni][3] + bs1;
            if (GELU) {
                v0 = 0.5f * v0 * (1.0f + erff(v0 * 0.70710678118654752f));
                v1 = 0.5f * v1 * (1.0f + erff(v1 * 0.70710678118654752f));
                v2 = 0.5f * v2 * (1.0f + erff(v2 * 0.70710678118654752f));
                v3 = 0.5f * v3 * (1.0f + erff(v3 * 0.70710678118654752f));
            }
            float2* p0 = (float2*)(C + (size_t)row * N + col);
            float2* p1 = (float2*)(C + (size_t)(row + 8) * N + col);
            *p0 = make_float2(v0, v1);
            *p1 = make_float2(v2, v3);
        }
}

template<int GELU>
__global__ __launch_bounds__(256, 2) void gemm_tf32(const float* __restrict__ A,
                                                    const float* __restrict__ W,
                                                    const float* __restrict__ bias,
                                                    float* __restrict__ C,
                                                    int N, int K) {
    extern __shared__ float dyn[];
    gemm_body<GELU>(A, W, bias, C, N, K, blockIdx.y * 128, blockIdx.x * 128,
                    dyn, dyn + 3*AST);
}

// fused QKV: blockIdx.x in [0,12): sel = bx>>2 picks {q,k,v}, (bx&3) n-tile.
__global__ __launch_bounds__(256, 2) void qkv_gemm(const float* __restrict__ A,
        const float* __restrict__ Wq, const float* __restrict__ bq,
        const float* __restrict__ Wk, const float* __restrict__ bk,
        const float* __restrict__ Wv, const float* __restrict__ bv,
        float* __restrict__ q, float* __restrict__ k, float* __restrict__ v) {
    extern __shared__ float dyn[];
    int sel = blockIdx.x >> 2;
    const float* W = sel == 0 ? Wq : (sel == 1 ? Wk : Wv);
    const float* bias = sel == 0 ? bq : (sel == 1 ? bk : bv);
    float* C = sel == 0 ? q : (sel == 1 ? k : v);
    gemm_body<0>(A, W, bias, C, D, D, blockIdx.y * 128, (blockIdx.x & 3) * 128,
                 dyn, dyn + 3*AST);
}

// ============================================================
// Fused attention: per (bh, 128-row i-strip) block does:
//   pass1: S = QK^T*SCALE (+prev), mask, write scores, track row-max
//   pass2: re-read scores (L2-hot), p = exp(s-m), row-sum, O = P@V, normalize
// ============================================================
__global__ __launch_bounds__(256) void attn_fused(const float* __restrict__ q,
                                                  const float* __restrict__ k,
                                                  const float* __restrict__ v,
                                                  float* __restrict__ scores,
                                                  float* __restrict__ ao,
                                                  int add_prev) {
    __shared__ float m_part[2][128];
    __shared__ float m_row[128];
    __shared__ float s_red[256];
    __shared__ float inv_row[128];
    __shared__ float u[8704];   // pass1: Qs[128][68] then Bs[2][16][136]; pass2: Ps+Vs

    int bh = blockIdx.y;
    int b = bh >> 3, h = bh & 7;
    int i0 = blockIdx.x * 128;
    int tid = threadIdx.x, lane = tid & 31, w = tid >> 5;
    int grp = lane >> 2, tg = lane & 3;
    int wm = (w >> 1) * 32, wn = (w & 1) * 64;

    // ---------------- pass 1 ----------------
    {   // stage Q strip [128][64] -> u (row stride 68)
        const float4* qsrc = (const float4*)(q + ((size_t)b * L + i0) * D + h * DK);
        #pragma unroll
        for (int it = 0; it < 8; it++) {
            int idx = tid + it * 256;          // 0..2047 float4s
            int row = idx >> 4, c4 = idx & 15;
            float4 t = qsrc[(size_t)row * (D / 4) + c4];
            float* dst = &u[row * 68 + c4 * 4];
            dst[0] = t.x; dst[1] = t.y; dst[2] = t.z; dst[3] = t.w;
        }
    }
    __syncthreads();
    unsigned af[8][2][4];                      // Q fragments live in regs all of pass1
    #pragma unroll
    for (int ks = 0; ks < 8; ks++)
        #pragma unroll
        for (int mi = 0; mi < 2; mi++) {
            int m = wm + mi * 16 + grp;
            af[ks][mi][0] = __float_as_uint(u[m * 68 + ks * 8 + tg]);
            af[ks][mi][1] = __float_as_uint(u[(m + 8) * 68 + ks * 8 + tg]);
            af[ks][mi][2] = __float_as_uint(u[m * 68 + ks * 8 + tg + 4]);
            af[ks][mi][3] = __float_as_uint(u[(m + 8) * 68 + ks * 8 + tg + 4]);
        }
    __syncthreads();

    float (*Bs)[16][136] = (float (*)[16][136])u;
    float rm[4] = {-3.4e38f, -3.4e38f, -3.4e38f, -3.4e38f};
    float acc[2][8][4];
    #pragma unroll
    for (int i = 0; i < 2; i++)
        #pragma unroll
        for (int j = 0; j < 8; j++)
            #pragma unroll
            for (int c = 0; c < 4; c++) acc[i][j][c] = 0.f;

    const float* kbase = k + (size_t)b * L * D + h * DK;
    float* sb = scores + (size_t)bh * L * L;
    int jj = tid >> 1, kc = (tid & 1) * 8;

    float4 ca, cb;
    {   // prefetch chunk (jt=0,c=0)
        const float* src = kbase + (size_t)jj * D + kc;
        ca = *(const float4*)(src); cb = *(const float4*)(src + 4);
        Bs[0][kc+0][jj]=ca.x; Bs[0][kc+1][jj]=ca.y;
        Bs[0][kc+2][jj]=ca.z; Bs[0][kc+3][jj]=ca.w;
        Bs[0][kc+4][jj]=cb.x; Bs[0][kc+5][jj]=cb.y;
        Bs[0][kc+6][jj]=cb.z; Bs[0][kc+7][jj]=cb.w;
    }
    __syncthreads();

    for (int jt = 0; jt < 8; jt++) {
        #pragma unroll
        for (int c = 0; c < 4; c++) {
            int buf = c & 1;
            int nch = jt * 4 + c + 1;
            float4 na, nb;
            if (nch < 32) {
                const float* src = kbase + (size_t)((nch >> 2) * 128 + jj) * D + (nch & 3) * 16 + kc;
                na = *(const float4*)(src); nb = *(const float4*)(src + 4);
            }
            #pragma unroll
            for (int ksl = 0; ksl < 2; ksl++) {
                unsigned bf[8][2];
                #pragma unroll
                for (int ni = 0; ni < 8; ni++) {
                    int n = wn + ni * 8 + grp;
                    bf[ni][0] = __float_as_uint(Bs[buf][ksl*8 + tg][n]);
                    bf[ni][1] = __float_as_uint(Bs[buf][ksl*8 + tg + 4][n]);
                }
                #pragma unroll
                for (int mi = 0; mi < 2; mi++)
                    #pragma unroll
                    for (int ni = 0; ni < 8; ni++)
                        mma8(acc[mi][ni], af[c*2 + ksl][mi], bf[ni]);
            }
            if (c == 3) {   // j-tile epilogue
                #pragma unroll
                for (int mi = 0; mi < 2; mi++)
                    #pragma unroll
                    for (int ni = 0; ni < 8; ni++) {
                        int gi = i0 + wm + mi * 16 + grp;
                        int gj = jt * 128 + wn + ni * 8 + tg * 2;
                        #pragma unroll
                        for (int rr = 0; rr < 2; rr++) {
                            int row = gi + rr * 8;
                            float s0 = acc[mi][ni][rr*2 + 0] * SCALE;
                            float s1 = acc[mi][ni][rr*2 + 1] * SCALE;
                            float2* p = (float2*)(sb + (size_t)row * L + gj);
                            if (add_prev) { float2 pv = *p; s0 += pv.x; s1 += pv.y; }
                            int d0 = row - gj;     d0 = d0 < 0 ? -d0 : d0;
                            int d1 = row - gj - 1; d1 = d1 < 0 ? -d1 : d1;
                            if (d0 < HWIN) s0 = NEG;
                            if (d1 < HWIN) s1 = NEG;
                            *p = make_float2(s0, s1);
                            rm[mi*2 + rr] = fmaxf(rm[mi*2 + rr], fmaxf(s0, s1));
                            acc[mi][ni][rr*2 + 0] = 0.f;
                            acc[mi][ni][rr*2 + 1] = 0.f;
                        }
                    }
            }
            if (nch < 32) {
                int nb2 = buf ^ 1;
                Bs[nb2][kc+0][jj]=na.x; Bs[nb2][kc+1][jj]=na.y;
                Bs[nb2][kc+2][jj]=na.z; Bs[nb2][kc+3][jj]=na.w;
                Bs[nb2][kc+4][jj]=nb.x; Bs[nb2][kc+5][jj]=nb.y;
                Bs[nb2][kc+6][jj]=nb.z; Bs[nb2][kc+7][jj]=nb.w;
            }
            __syncthreads();
        }
    }

    // reduce row max: over quad (tg) lanes, then across the 2 warps per row set
    #pragma unroll
    for (int mi = 0; mi < 2; mi++)
        #pragma unroll
        for (int rr = 0; rr < 2; rr++) {
            float vv = rm[mi*2 + rr];
            vv = fmaxf(vv, __shfl_xor_sync(0xffffffffu, vv, 1));
            vv = fmaxf(vv, __shfl_xor_sync(0xffffffffu, vv, 2));
            if (tg == 0) m_part[w & 1][wm + mi*16 + grp + rr*8] = vv;
        }
    __syncthreads();
    if (tid < 128) m_row[tid] = fmaxf(m_part[0][tid], m_part[1][tid]);
    __syncthreads();

    // ---------------- pass 2: O = softmax(S) @ V ----------------
    int ar = tid >> 1, ac = (tid & 1) * 8;
    int br = tid >> 4, bc = (tid & 15) * 4;
    int wn2 = (w & 1) * 32;
    float (*Ps)[128][20] = (float (*)[128][20])u;
    float (*Vs)[16][72]  = (float (*)[16][72])(u + 5120);
    const float* Sp = sb + (size_t)(i0 + ar) * L + ac;
    const float* Vp = v + (size_t)b * L * D + h * DK + (size_t)br * D + bc;
    float mrow = m_row[ar];
    float sum_part = 0.f;
    float acc2[2][4][4];
    #pragma unroll
    for (int i = 0; i < 2; i++)
        #pragma unroll
        for (int j = 0; j < 4; j++)
            #pragma unroll
            for (int c = 0; c < 4; c++) acc2[i][j][c] = 0.f;

    {   // stage chunk 0
        float4 s0 = *(const float4*)(Sp), s1 = *(const float4*)(Sp + 4);
        float4 vv = *(const float4*)(Vp);
        float p0=__expf(s0.x-mrow), p1=__expf(s0.y-mrow), p2=__expf(s0.z-mrow), p3=__expf(s0.w-mrow);
        float p4=__expf(s1.x-mrow), p5=__expf(s1.y-mrow), p6=__expf(s1.z-mrow), p7=__expf(s1.w-mrow);
        sum_part += p0+p1+p2+p3+p4+p5+p6+p7;
        float* pd = &Ps[0][ar][ac];
        pd[0]=p0; pd[1]=p1; pd[2]=p2; pd[3]=p3;
        pd[4]=p4; pd[5]=p5; pd[6]=p6; pd[7]=p7;
        Vs[0][br][bc+0]=vv.x; Vs[0][br][bc+1]=vv.y;
        Vs[0][br][bc+2]=vv.z; Vs[0][br][bc+3]=vv.w;
    }
    __syncthreads();

    for (int t = 0; t < 64; t++) {
        int buf = t & 1;
        float4 ns0, ns1, nv;
        if (t + 1 < 64) {
            ns0 = *(const float4*)(Sp + (t+1)*16);
            ns1 = *(const float4*)(Sp + (t+1)*16 + 4);
            nv  = *(const float4*)(Vp + (size_t)(t+1) * 16 * D);
        }
        #pragma unroll
        for (int ksl = 0; ksl < 2; ksl++) {
            unsigned a2[2][4], b2[4][2];
            #pragma unroll
            for (int mi = 0; mi < 2; mi++) {
                int m = wm + mi * 16 + grp;
                a2[mi][0] = __float_as_uint(Ps[buf][m][ksl*8 + tg]);
                a2[mi][1] = __float_as_uint(Ps[buf][m + 8][ksl*8 + tg]);
                a2[mi][2] = __float_as_uint(Ps[buf][m][ksl*8 + tg + 4]);
                a2[mi][3] = __float_as_uint(Ps[buf][m + 8][ksl*8 + tg + 4]);
            }
            #pragma unroll
            for (int ni = 0; ni < 4; ni++) {
                int n = wn2 + ni * 8 + grp;
                b2[ni][0] = __float_as_uint(Vs[buf][ksl*8 + tg][n]);
                b2[ni][1] = __float_as_uint(Vs[buf][ksl*8 + tg + 4][n]);
            }
            #pragma unroll
            for (int mi = 0; mi < 2; mi++)
                #pragma unroll
                for (int ni = 0; ni < 4; ni++)
                    mma8(acc2[mi][ni], a2[mi], b2[ni]);
        }
        if (t + 1 < 64) {
            int nb2 = buf ^ 1;
            float p0=__expf(ns0.x-mrow), p1=__expf(ns0.y-mrow), p2=__expf(ns0.z-mrow), p3=__expf(ns0.w-mrow);
            float p4=__expf(ns1.x-mrow), p5=__expf(ns1.y-mrow), p6=__expf(ns1.z-mrow), p7=__expf(ns1.w-mrow);
            sum_part += p0+p1+p2+p3+p4+p5+p6+p7;
            float* pd = &Ps[nb2][ar][ac];
            pd[0]=p0; pd[1]=p1; pd[2]=p2; pd[3]=p3;
            pd[4]=p4; pd[5]=p5; pd[6]=p6; pd[7]=p7;
            Vs[nb2][br][bc+0]=nv.x; Vs[nb2][br][bc+1]=nv.y;
            Vs[nb2][br][bc+2]=nv.z; Vs[nb2][br][bc+3]=nv.w;
        }
        __syncthreads();
    }

    s_red[tid] = sum_part;
    __syncthreads();
    if (tid < 128) inv_row[tid] = 1.0f / (s_red[2*tid] + s_red[2*tid + 1]);
    __syncthreads();

    float* ob = ao + (size_t)b * L * D + h * DK;
    #pragma unroll
    for (int mi = 0; mi < 2; mi++)
        #pragma unroll
        for (int ni = 0; ni < 4; ni++) {
            int rl = wm + mi * 16 + grp;
            int col = wn2 + ni * 8 + tg * 2;
            float iv0 = inv_row[rl], iv1 = inv_row[rl + 8];
            float2* p0 = (float2*)(ob + (size_t)(i0 + rl) * D + col);
            float2* p1 = (float2*)(ob + (size_t)(i0 + rl + 8) * D + col);
            *p0 = make_float2(acc2[mi][ni][0] * iv0, acc2[mi][ni][1] * iv0);
            *p1 = make_float2(acc2[mi][ni][2] * iv1, acc2[mi][ni][3] * iv1);
        }
}

// ============================================================
// out = LayerNorm(x + r) * gamma + beta. One block (128 thr) per row of 512.
// ============================================================
__global__ void addln_kernel(const float* __restrict__ x, const float* __restrict__ r,
                             const float* __restrict__ gam, const float* __restrict__ bet,
                             float* __restrict__ out) {
    int row = blockIdx.x;
    int tid = threadIdx.x;  // 128
    const float4* xp = (const float4*)(x + (size_t)row * D);
    const float4* rp = (const float4*)(r + (size_t)row * D);
    float4 a = xp[tid], b4 = rp[tid];
    float e0 = a.x + b4.x, e1 = a.y + b4.y, e2 = a.z + b4.z, e3 = a.w + b4.w;
    float s = e0 + e1 + e2 + e3;
    float qq = e0*e0 + e1*e1 + e2*e2 + e3*e3;
    __shared__ float rs[4], rq[4];
    #pragma unroll
    for (int off = 16; off; off >>= 1) {
        s  += __shfl_xor_sync(0xffffffffu, s, off);
        qq += __shfl_xor_sync(0xffffffffu, qq, off);
    }
    if ((tid & 31) == 0) { rs[tid >> 5] = s; rq[tid >> 5] = qq; }
    __syncthreads();
    s  = rs[0] + rs[1] + rs[2] + rs[3];
    qq = rq[0] + rq[1] + rq[2] + rq[3];
    float mean = s * (1.0f / D);
    float var  = qq * (1.0f / D) - mean * mean;
    float inv  = rsqrtf(var + EPS);
    float4 g4 = ((const float4*)gam)[tid];
    float4 bb = ((const float4*)bet)[tid];
    float4 ov;
    ov.x = (e0 - mean) * inv * g4.x + bb.x;
    ov.y = (e1 - mean) * inv * g4.y + bb.y;
    ov.z = (e2 - mean) * inv * g4.z + bb.z;
    ov.w = (e3 - mean) * inv * g4.w + bb.w;
    ((float4*)(out + (size_t)row * D))[tid] = ov;
}

// ============================================================
extern "C" void kernel_launch(void* const* d_in, const int* in_sizes, int n_in,
                              void* d_out, int out_size) {
    const float* src = (const float*)d_in[0];
    const float* Wq = (const float*)d_in[1];  const float* bq = (const float*)d_in[2];
    const float* Wk = (const float*)d_in[3];  const float* bk = (const float*)d_in[4];
    const float* Wv = (const float*)d_in[5];  const float* bv = (const float*)d_in[6];
    const float* Wo = (const float*)d_in[7];  const float* bo = (const float*)d_in[8];
    const float* W1 = (const float*)d_in[9];  const float* b1 = (const float*)d_in[10];
    const float* W2 = (const float*)d_in[11]; const float* b2 = (const float*)d_in[12];
    const float* ln1g = (const float*)d_in[13]; const float* ln1b = (const float*)d_in[14];
    const float* ln2g = (const float*)d_in[15]; const float* ln2b = (const float*)d_in[16];

    float *q, *k, *v, *x, *tmp, *ao, *ff, *sc;
    cudaGetSymbolAddress((void**)&q,  g_q);
    cudaGetSymbolAddress((void**)&k,  g_k);
    cudaGetSymbolAddress((void**)&v,  g_v);
    cudaGetSymbolAddress((void**)&x,  g_x);
    cudaGetSymbolAddress((void**)&tmp, g_tmp);
    cudaGetSymbolAddress((void**)&ao, g_ao);
    cudaGetSymbolAddress((void**)&ff, g_ff);
    cudaGetSymbolAddress((void**)&sc, g_scores);

    cudaFuncSetAttribute(gemm_tf32<0>, cudaFuncAttributeMaxDynamicSharedMemorySize, GEMM_SMEM);
    cudaFuncSetAttribute(gemm_tf32<1>, cudaFuncAttributeMaxDynamicSharedMemorySize, GEMM_SMEM);
    cudaFuncSetAttribute(qkv_gemm,     cudaFuncAttributeMaxDynamicSharedMemorySize, GEMM_SMEM);

    dim3 gD(D/128, ROWS/128);     // 4 x 32
    dim3 gDF(DF/128, ROWS/128);   // 16 x 32
    dim3 gQKV(12, ROWS/128);      // 12 x 32
    dim3 gA(L/128, BH);           // 8 x 32

    const float* xin = src;
    for (int l = 0; l < NL; l++) {
        qkv_gemm<<<gQKV, 256, GEMM_SMEM>>>(xin,
            Wq + (size_t)l*D*D, bq + (size_t)l*D,
            Wk + (size_t)l*D*D, bk + (size_t)l*D,
            Wv + (size_t)l*D*D, bv + (size_t)l*D, q, k, v);
        attn_fused<<<gA, 256>>>(q, k, v, sc, ao, l > 0 ? 1 : 0);
        gemm_tf32<0><<<gD, 256, GEMM_SMEM>>>(ao, Wo + (size_t)l*D*D, bo + (size_t)l*D, tmp, D, D);
        addln_kernel<<<ROWS, 128>>>(xin, tmp, ln1g + (size_t)l*D, ln1b + (size_t)l*D, x);
        gemm_tf32<1><<<gDF, 256, GEMM_SMEM>>>(x, W1 + (size_t)l*D*DF, b1 + (size_t)l*DF, ff, DF, D);
        gemm_tf32<0><<<gD, 256, GEMM_SMEM>>>(ff, W2 + (size_t)l*DF*D, b2 + (size_t)l*D, tmp, D, DF);
        float* lnout = (l == NL-1) ? (float*)d_out : x;
        addln_kernel<<<ROWS, 128>>>(x, tmp, ln2g + (size_t)l*D, ln2b + (size_t)l*D, lnout);
        xin = x;
    }
}